// round 5
// baseline (speedup 1.0000x reference)
#include <cuda_runtime.h>

// Shapes are fixed by the problem definition.
constexpr int Lc = 2048;
constexpr int Ic = 32000;
constexpr int Dc = 256;

// Scratch: posEmbed rows {L-2, L-1}, dense1 rows, attention rows.
__device__ float g_p[2][Dc];
__device__ float g_d[2][Dc];
__device__ float g_a[2][Dc];

// K0: seed g_p with the PE rows (so K1's GEMV atomics land on top of the bias),
// zero dense1/attention partial accumulators. 1 block x 256 threads.
__global__ void k0_init(const float* __restrict__ PE) {
    int c = threadIdx.x;
    g_p[0][c] = PE[(size_t)(Lc - 2) * Dc + c];
    g_p[1][c] = PE[(size_t)(Lc - 1) * Dc + c];
    g_d[0][c] = 0.f; g_d[1][c] = 0.f;
    g_a[0][c] = 0.f; g_a[1][c] = 0.f;
}

// K1: p_k += x[L-2+k] @ DE  (dual GEMV over the 32000x256 DE matrix).
// grid 500 blocks x 256 threads; each block handles 64 rows of DE.
// Thread t owns output column t; DE row reads are fully coalesced (1 KB/row).
__global__ void __launch_bounds__(256) k1_posembed(const float* __restrict__ x,
                                                   const float* __restrict__ DE) {
    __shared__ float sx0[64], sx1[64];
    int t = threadIdx.x;
    int r0 = blockIdx.x * 64;
    if (t < 64) {
        sx0[t] = x[(size_t)(Lc - 2) * Ic + r0 + t];
    } else if (t < 128) {
        sx1[t - 64] = x[(size_t)(Lc - 1) * Ic + r0 + (t - 64)];
    }
    __syncthreads();
    float a0 = 0.f, a1 = 0.f;
    const float* de = DE + (size_t)r0 * Dc + t;
#pragma unroll 8
    for (int r = 0; r < 64; ++r) {
        float v = de[(size_t)r * Dc];
        a0 += sx0[r] * v;
        a1 += sx1[r] * v;
    }
    atomicAdd(&g_p[0][t], a0);
    atomicAdd(&g_p[1][t], a1);
}

// K2: dense1 rows = concat(posEmbed_row, pool1_row) @ D1, k-split across blocks.
// pool1[L-2] = (p0+p1)/ (L-1), pool1[L-1] = p1 / L.
// grid 16 blocks x 256 threads; block b handles k in [32b, 32b+32).
__global__ void __launch_bounds__(256) k2_dense1(const float* __restrict__ D1w) {
    __shared__ float sc0[32], sc1[32];
    int t = threadIdx.x;
    int kbase = blockIdx.x * 32;
    if (t < 32) {
        int k = kbase + t;
        float c0, c1;
        if (k < Dc) {
            c0 = g_p[0][k];
            c1 = g_p[1][k];
        } else {
            int kk = k - Dc;
            c0 = (g_p[0][kk] + g_p[1][kk]) * (1.0f / (float)(Lc - 1));
            c1 = g_p[1][kk] * (1.0f / (float)Lc);
        }
        sc0[t] = c0;
        sc1[t] = c1;
    }
    __syncthreads();
    float a0 = 0.f, a1 = 0.f;
#pragma unroll
    for (int kk = 0; kk < 32; ++kk) {
        float v = D1w[(size_t)(kbase + kk) * Dc + t];
        a0 += sc0[kk] * v;
        a1 += sc1[kk] * v;
    }
    atomicAdd(&g_d[0][t], a0);
    atomicAdd(&g_d[1][t], a1);
}

// K3: attention rows = concat(dense1_row, pool2_row) @ Att, same k-split.
// pool2[L-2] = (d0+d1)/(L-1), pool2[L-1] = d1 / L.
__global__ void __launch_bounds__(256) k3_attention(const float* __restrict__ Attw) {
    __shared__ float sc0[32], sc1[32];
    int t = threadIdx.x;
    int kbase = blockIdx.x * 32;
    if (t < 32) {
        int k = kbase + t;
        float c0, c1;
        if (k < Dc) {
            c0 = g_d[0][k];
            c1 = g_d[1][k];
        } else {
            int kk = k - Dc;
            c0 = (g_d[0][kk] + g_d[1][kk]) * (1.0f / (float)(Lc - 1));
            c1 = g_d[1][kk] * (1.0f / (float)Lc);
        }
        sc0[t] = c0;
        sc1[t] = c1;
    }
    __syncthreads();
    float a0 = 0.f, a1 = 0.f;
#pragma unroll
    for (int kk = 0; kk < 32; ++kk) {
        float v = Attw[(size_t)(kbase + kk) * Dc + t];
        a0 += sc0[kk] * v;
        a1 += sc1[kk] * v;
    }
    atomicAdd(&g_a[0][t], a0);
    atomicAdd(&g_a[1][t], a1);
}

// K4: out[i] = sum_d w[d] * D2[d, i], with
// w = d0*a0 + d1*a1 (the two surviving weighted rows, summed by SA.T).
// grid 125 blocks x 256 threads; thread = one output column; coalesced D2 reads.
__global__ void __launch_bounds__(256) k4_out(const float* __restrict__ D2w,
                                              float* __restrict__ out) {
    __shared__ float w[Dc];
    int t = threadIdx.x;
    w[t] = g_d[0][t] * g_a[0][t] + g_d[1][t] * g_a[1][t];
    __syncthreads();
    int i = blockIdx.x * 256 + t;
    float acc = 0.f;
#pragma unroll 8
    for (int d = 0; d < Dc; ++d) {
        acc += w[d] * D2w[(size_t)d * Ic + i];
    }
    out[i] = acc;
}

extern "C" void kernel_launch(void* const* d_in, const int* in_sizes, int n_in,
                              void* d_out, int out_size) {
    const float* x   = (const float*)d_in[0];  // [L, I]
    const float* DE  = (const float*)d_in[1];  // [I, D]
    const float* PE  = (const float*)d_in[2];  // [L, D]
    const float* D1w = (const float*)d_in[3];  // [2D, D]
    const float* D2w = (const float*)d_in[4];  // [D, I]
    const float* Att = (const float*)d_in[5];  // [2D, D]
    float* out = (float*)d_out;                // [1, I]
    (void)in_sizes; (void)n_in; (void)out_size;

    k0_init<<<1, 256>>>(PE);
    k1_posembed<<<500, 256>>>(x, DE);
    k2_dense1<<<16, 256>>>(D1w);
    k3_attention<<<16, 256>>>(Att);
    k4_out<<<125, 256>>>(D2w, out);
}